// round 17
// baseline (speedup 1.0000x reference)
#include <cuda_runtime.h>

// ---------------------------------------------------------------------------
// TNModel binary-tree TN, B=65536. Round 17: single launch, producer+consumer
// grid. Blocks 0..2735: eighth-subtree producers (R14 k1 body, SPT=3,
// 5 CTAs/SM). Blocks 2736..3759: merge consumers (R11 side-split body) that
// acquire-spin on per-192-sample counters and run overlapped with the
// producer tail. Producer/merge bodies are __noinline__ so register
// allocation is max(paths), not their union (the R8/R9 spill cause).
// Counters are zeroed by a cudaMemsetAsync node each launch.
// ---------------------------------------------------------------------------

#define NB       65536
#define T1       64
#define SPT      3
#define SPB      (T1 * SPT)          // 192
#define BLK_E    342                 // ceil(NB / SPB)
#define NPROD    (8 * BLK_E)         // 2736 producer CTAs
#define NMERGE   1024                // merge CTAs (32 sample-pairs each)
#define NBLOCKS  (NPROD + NMERGE)    // 3760
#define HALF     (NB / 2)

// producer shared-memory float offsets (eighth-tree weights)
#define E7 0                      // 16 x 16   =  256
#define E6 (E7 + 256)             //  8 x 128  = 1024
#define E5 (E6 + 1024)            //  4 x 512  = 2048
#define E4 (E5 + 2048)            //  2 x 512  = 1024
#define E3 (E4 + 1024)            //  1 x 512  =  512
#define SMEM_FLOATS (E3 + 512)    // 4864 floats = 19456 bytes

// merge shared-memory float offsets (inside the same 4864-float window)
#define MW2 0                     // 2048
#define MW1 2048                  // 1024
#define MW0 3072                  // 128
#define MXA 3328                  // 288 (hR of sample A)
#define MXB (MXA + 288)           // 288 (hL of sample B)  -> 3904 total

typedef unsigned long long ull;

__device__ float4 g_ebuf[8 * NB * 2];   // [eighth][sample][2 x float4]
__device__ unsigned int g_ctr[BLK_E];   // zeroed via memset node each launch

__device__ __forceinline__ ull ffma2(ull a, ull b, ull c) {
    ull d;
    asm("fma.rn.f32x2 %0, %1, %2, %3;" : "=l"(d) : "l"(a), "l"(b), "l"(c));
    return d;
}
__device__ __forceinline__ ull bcast2(float x) {
    ull r;
    asm("mov.b64 %0, {%1, %1};" : "=l"(r) : "f"(x));
    return r;
}
__device__ __forceinline__ void unpack2(ull v, float& lo, float& hi) {
    asm("mov.b64 {%0, %1}, %2;" : "=f"(lo), "=f"(hi) : "l"(v));
}
__device__ __forceinline__ void cp8(float* d, const float* s) {
#pragma unroll
    for (int k = 0; k < 8; ++k) d[k] = s[k];
}
__device__ __forceinline__ unsigned ld_acq(const unsigned* p) {
    unsigned v;
    asm volatile("ld.acquire.gpu.u32 %0, [%1];" : "=r"(v) : "l"(p));
    return v;
}

// ---- 3-sample primitives (producer) ----------------------------------------

__device__ __forceinline__ void leaf3(float4 qa, float4 qb, float4 qc,
                                      const float* __restrict__ w,
                                      float* hA, float* hB, float* hC) {
    ull cA0 = 0, cA1 = 0, cB0 = 0, cB1 = 0, cC0 = 0, cC1 = 0;
    float eA[2] = {qa.x, qa.y}, oA[2] = {qa.z, qa.w};
    float eB[2] = {qb.x, qb.y}, oB[2] = {qb.z, qb.w};
    float eC[2] = {qc.x, qc.y}, oC[2] = {qc.z, qc.w};
#pragma unroll
    for (int i = 0; i < 2; ++i) {
#pragma unroll
        for (int j = 0; j < 2; ++j) {
            const ulonglong2 W = *reinterpret_cast<const ulonglong2*>(w + (i * 2 + j) * 4);
            ull p = bcast2(eA[i] * oA[j]);
            cA0 = ffma2(p, W.x, cA0);  cA1 = ffma2(p, W.y, cA1);
            p = bcast2(eB[i] * oB[j]);
            cB0 = ffma2(p, W.x, cB0);  cB1 = ffma2(p, W.y, cB1);
            p = bcast2(eC[i] * oC[j]);
            cC0 = ffma2(p, W.x, cC0);  cC1 = ffma2(p, W.y, cC1);
        }
    }
    unpack2(cA0, hA[0], hA[1]);  unpack2(cA1, hA[2], hA[3]);
    unpack2(cB0, hB[0], hB[1]);  unpack2(cB1, hB[2], hB[3]);
    unpack2(cC0, hC[0], hC[1]);  unpack2(cC1, hC[2], hC[3]);
}

__device__ __forceinline__ void contract448_3(const float* aA, const float* bA,
                                              const float* aB, const float* bB,
                                              const float* aC, const float* bC,
                                              const float* __restrict__ w,
                                              float* outA, float* outB, float* outC) {
    ull cA[4] = {0,0,0,0}, cB[4] = {0,0,0,0}, cC[4] = {0,0,0,0};
#pragma unroll
    for (int i = 0; i < 4; ++i) {
        ull tA[4] = {0,0,0,0}, tB[4] = {0,0,0,0}, tC[4] = {0,0,0,0};
#pragma unroll
        for (int j = 0; j < 4; ++j) {
            const ulonglong2* wp = reinterpret_cast<const ulonglong2*>(w + (i * 4 + j) * 8);
            ulonglong2 W01 = wp[0];
            ulonglong2 W23 = wp[1];
            ull bb = bcast2(bA[j]);
            tA[0] = ffma2(bb, W01.x, tA[0]);  tA[1] = ffma2(bb, W01.y, tA[1]);
            tA[2] = ffma2(bb, W23.x, tA[2]);  tA[3] = ffma2(bb, W23.y, tA[3]);
            bb = bcast2(bB[j]);
            tB[0] = ffma2(bb, W01.x, tB[0]);  tB[1] = ffma2(bb, W01.y, tB[1]);
            tB[2] = ffma2(bb, W23.x, tB[2]);  tB[3] = ffma2(bb, W23.y, tB[3]);
            bb = bcast2(bC[j]);
            tC[0] = ffma2(bb, W01.x, tC[0]);  tC[1] = ffma2(bb, W01.y, tC[1]);
            tC[2] = ffma2(bb, W23.x, tC[2]);  tC[3] = ffma2(bb, W23.y, tC[3]);
        }
        ull ai = bcast2(aA[i]);
        cA[0] = ffma2(ai, tA[0], cA[0]);  cA[1] = ffma2(ai, tA[1], cA[1]);
        cA[2] = ffma2(ai, tA[2], cA[2]);  cA[3] = ffma2(ai, tA[3], cA[3]);
        ai = bcast2(aB[i]);
        cB[0] = ffma2(ai, tB[0], cB[0]);  cB[1] = ffma2(ai, tB[1], cB[1]);
        cB[2] = ffma2(ai, tB[2], cB[2]);  cB[3] = ffma2(ai, tB[3], cB[3]);
        ai = bcast2(aC[i]);
        cC[0] = ffma2(ai, tC[0], cC[0]);  cC[1] = ffma2(ai, tC[1], cC[1]);
        cC[2] = ffma2(ai, tC[2], cC[2]);  cC[3] = ffma2(ai, tC[3], cC[3]);
    }
    unpack2(cA[0], outA[0], outA[1]);  unpack2(cA[1], outA[2], outA[3]);
    unpack2(cA[2], outA[4], outA[5]);  unpack2(cA[3], outA[6], outA[7]);
    unpack2(cB[0], outB[0], outB[1]);  unpack2(cB[1], outB[2], outB[3]);
    unpack2(cB[2], outB[4], outB[5]);  unpack2(cB[3], outB[6], outB[7]);
    unpack2(cC[0], outC[0], outC[1]);  unpack2(cC[1], outC[2], outC[3]);
    unpack2(cC[2], outC[4], outC[5]);  unpack2(cC[3], outC[6], outC[7]);
}

__device__ __forceinline__ void contract888_3(const float* aA, const float* bA,
                                              const float* aB, const float* bB,
                                              const float* aC, const float* bC,
                                              const float* __restrict__ w,
                                              float* outA, float* outB, float* outC) {
    const ulonglong2* wp = reinterpret_cast<const ulonglong2*>(w);
    ull cA[4] = {0,0,0,0}, cB[4] = {0,0,0,0}, cC[4] = {0,0,0,0};
    ulonglong2 W0a = wp[0], W0b = wp[1];
    ulonglong2 W1a = wp[2], W1b = wp[3];
#pragma unroll
    for (int i = 0; i < 8; ++i) {
        ull tA[4] = {0,0,0,0}, tB[4] = {0,0,0,0}, tC[4] = {0,0,0,0};
#pragma unroll
        for (int j = 0; j < 8; ++j) {
            const int nidx = i * 8 + j + 2;
            ulonglong2 nWa, nWb;
            if (nidx < 64) {
                nWa = wp[2 * nidx];
                nWb = wp[2 * nidx + 1];
            }
            ull bb = bcast2(bA[j]);
            tA[0] = ffma2(bb, W0a.x, tA[0]);  tA[1] = ffma2(bb, W0a.y, tA[1]);
            tA[2] = ffma2(bb, W0b.x, tA[2]);  tA[3] = ffma2(bb, W0b.y, tA[3]);
            bb = bcast2(bB[j]);
            tB[0] = ffma2(bb, W0a.x, tB[0]);  tB[1] = ffma2(bb, W0a.y, tB[1]);
            tB[2] = ffma2(bb, W0b.x, tB[2]);  tB[3] = ffma2(bb, W0b.y, tB[3]);
            bb = bcast2(bC[j]);
            tC[0] = ffma2(bb, W0a.x, tC[0]);  tC[1] = ffma2(bb, W0a.y, tC[1]);
            tC[2] = ffma2(bb, W0b.x, tC[2]);  tC[3] = ffma2(bb, W0b.y, tC[3]);
            W0a = W1a;  W0b = W1b;
            if (nidx < 64) { W1a = nWa; W1b = nWb; }
        }
        ull ai = bcast2(aA[i]);
        cA[0] = ffma2(ai, tA[0], cA[0]);  cA[1] = ffma2(ai, tA[1], cA[1]);
        cA[2] = ffma2(ai, tA[2], cA[2]);  cA[3] = ffma2(ai, tA[3], cA[3]);
        ai = bcast2(aB[i]);
        cB[0] = ffma2(ai, tB[0], cB[0]);  cB[1] = ffma2(ai, tB[1], cB[1]);
        cB[2] = ffma2(ai, tB[2], cB[2]);  cB[3] = ffma2(ai, tB[3], cB[3]);
        ai = bcast2(aC[i]);
        cC[0] = ffma2(ai, tC[0], cC[0]);  cC[1] = ffma2(ai, tC[1], cC[1]);
        cC[2] = ffma2(ai, tC[2], cC[2]);  cC[3] = ffma2(ai, tC[3], cC[3]);
    }
    unpack2(cA[0], outA[0], outA[1]);  unpack2(cA[1], outA[2], outA[3]);
    unpack2(cA[2], outA[4], outA[5]);  unpack2(cA[3], outA[6], outA[7]);
    unpack2(cB[0], outB[0], outB[1]);  unpack2(cB[1], outB[2], outB[3]);
    unpack2(cB[2], outB[4], outB[5]);  unpack2(cB[3], outB[6], outB[7]);
    unpack2(cC[0], outC[0], outC[1]);  unpack2(cC[1], outC[2], outC[3]);
    unpack2(cC[2], outC[4], outC[5]);  unpack2(cC[3], outC[6], outC[7]);
}

// ---- 2/1-sample 8x8x8 (merge path, smem weights, prefetch-2) ---------------
__device__ __forceinline__ void contract888_2(const float* aA, const float* bA,
                                              const float* aB, const float* bB,
                                              const float* __restrict__ w,
                                              float* outA, float* outB) {
    const ulonglong2* wp = reinterpret_cast<const ulonglong2*>(w);
    ull cA[4] = {0,0,0,0}, cB[4] = {0,0,0,0};
    ulonglong2 W0a = wp[0], W0b = wp[1];
    ulonglong2 W1a = wp[2], W1b = wp[3];
#pragma unroll
    for (int i = 0; i < 8; ++i) {
        ull tA[4] = {0,0,0,0}, tB[4] = {0,0,0,0};
#pragma unroll
        for (int j = 0; j < 8; ++j) {
            const int nidx = i * 8 + j + 2;
            ulonglong2 nWa, nWb;
            if (nidx < 64) {
                nWa = wp[2 * nidx];
                nWb = wp[2 * nidx + 1];
            }
            ull bb = bcast2(bA[j]);
            tA[0] = ffma2(bb, W0a.x, tA[0]);  tA[1] = ffma2(bb, W0a.y, tA[1]);
            tA[2] = ffma2(bb, W0b.x, tA[2]);  tA[3] = ffma2(bb, W0b.y, tA[3]);
            bb = bcast2(bB[j]);
            tB[0] = ffma2(bb, W0a.x, tB[0]);  tB[1] = ffma2(bb, W0a.y, tB[1]);
            tB[2] = ffma2(bb, W0b.x, tB[2]);  tB[3] = ffma2(bb, W0b.y, tB[3]);
            W0a = W1a;  W0b = W1b;
            if (nidx < 64) { W1a = nWa; W1b = nWb; }
        }
        ull ai = bcast2(aA[i]);
        cA[0] = ffma2(ai, tA[0], cA[0]);  cA[1] = ffma2(ai, tA[1], cA[1]);
        cA[2] = ffma2(ai, tA[2], cA[2]);  cA[3] = ffma2(ai, tA[3], cA[3]);
        ai = bcast2(aB[i]);
        cB[0] = ffma2(ai, tB[0], cB[0]);  cB[1] = ffma2(ai, tB[1], cB[1]);
        cB[2] = ffma2(ai, tB[2], cB[2]);  cB[3] = ffma2(ai, tB[3], cB[3]);
    }
    unpack2(cA[0], outA[0], outA[1]);  unpack2(cA[1], outA[2], outA[3]);
    unpack2(cA[2], outA[4], outA[5]);  unpack2(cA[3], outA[6], outA[7]);
    unpack2(cB[0], outB[0], outB[1]);  unpack2(cB[1], outB[2], outB[3]);
    unpack2(cB[2], outB[4], outB[5]);  unpack2(cB[3], outB[6], outB[7]);
}

__device__ __forceinline__ void scopy4(float* dst, const float* __restrict__ src, int n4) {
    const float4* s = reinterpret_cast<const float4*>(src);
    float4* d = reinterpret_cast<float4*>(dst);
    for (int i = threadIdx.x; i < n4; i += blockDim.x) d[i] = s[i];
}

__device__ __forceinline__ void store_pair(float4* buf, int b, const float* v) {
    buf[(size_t)b * 2 + 0] = make_float4(v[0], v[1], v[2], v[3]);
    buf[(size_t)b * 2 + 1] = make_float4(v[4], v[5], v[6], v[7]);
}
__device__ __forceinline__ void load_pair(int e, int b, float* v) {
    const float4* p = g_ebuf + ((size_t)e * NB + b) * 2;
    float4 p0 = p[0];
    float4 p1 = p[1];
    v[0] = p0.x; v[1] = p0.y; v[2] = p0.z; v[3] = p0.w;
    v[4] = p1.x; v[5] = p1.y; v[6] = p1.z; v[7] = p1.w;
}

// ------------------------------ producer path -------------------------------
__device__ __noinline__ void producer_path(int bid, float* sw,
                                           const float* __restrict__ x,
                                           const float* __restrict__ w7,
                                           const float* __restrict__ w6,
                                           const float* __restrict__ w5,
                                           const float* __restrict__ w4,
                                           const float* __restrict__ w3) {
    const int e   = bid / BLK_E;
    const int blk = bid - e * BLK_E;

    scopy4(sw + E7, w7 + e * 256,   256 / 4);
    scopy4(sw + E6, w6 + e * 1024, 1024 / 4);
    scopy4(sw + E5, w5 + e * 2048, 2048 / 4);
    scopy4(sw + E4, w4 + e * 1024, 1024 / 4);
    scopy4(sw + E3, w3 + e * 512,   512 / 4);
    __syncthreads();

    const int b0 = blk * SPB + threadIdx.x;
    int b1 = b0 + T1;
    int b2 = b0 + 2 * T1;
    if (b1 >= NB) b1 = b0;
    if (b2 >= NB) b2 = b0;

    const float4* xA = reinterpret_cast<const float4*>(x) + (size_t)b0 * 128 + e * 16;
    const float4* xB = reinterpret_cast<const float4*>(x) + (size_t)b1 * 128 + e * 16;
    const float4* xC = reinterpret_cast<const float4*>(x) + (size_t)b2 * 128 + e * 16;

    float stkA0[8], stkA1[8], stkA2[8];
    float stkB0[8], stkB1[8], stkB2[8];
    float stkC0[8], stkC1[8], stkC2[8];

#pragma unroll 1
    for (int m = 0; m < 8; ++m) {
        float4 qA0 = __ldcs(xA + 2 * m);
        float4 qA1 = __ldcs(xA + 2 * m + 1);
        float4 qB0 = __ldcs(xB + 2 * m);
        float4 qB1 = __ldcs(xB + 2 * m + 1);
        float4 qC0 = __ldcs(xC + 2 * m);
        float4 qC1 = __ldcs(xC + 2 * m + 1);

        float laA[4], lbA[4], laB[4], lbB[4], laC[4], lbC[4];
        leaf3(qA0, qB0, qC0, sw + E7 + (2 * m) * 16, laA, laB, laC);
        leaf3(qA1, qB1, qC1, sw + E7 + (2 * m + 1) * 16, lbA, lbB, lbC);

        float curA[8], curB[8], curC[8];
        contract448_3(laA, lbA, laB, lbB, laC, lbC, sw + E6 + m * 128,
                      curA, curB, curC);

        if (!(m & 1)) {
            cp8(stkA0, curA);  cp8(stkB0, curB);  cp8(stkC0, curC);
        } else {
            contract888_3(stkA0, curA, stkB0, curB, stkC0, curC,
                          sw + E5 + (m >> 1) * 512, curA, curB, curC);
            if (!((m >> 1) & 1)) {
                cp8(stkA1, curA);  cp8(stkB1, curB);  cp8(stkC1, curC);
            } else {
                contract888_3(stkA1, curA, stkB1, curB, stkC1, curC,
                              sw + E4 + (m >> 2) * 512, curA, curB, curC);
                if (!((m >> 2) & 1)) {
                    cp8(stkA2, curA);  cp8(stkB2, curB);  cp8(stkC2, curC);
                } else {
                    contract888_3(stkA2, curA, stkB2, curB, stkC2, curC,
                                  sw + E3, curA, curB, curC);
                    float4* eb = g_ebuf + ((size_t)e * NB) * 2;
                    store_pair(eb, b0, curA);
                    store_pair(eb, b1, curB);
                    store_pair(eb, b2, curC);
                }
            }
        }
    }

    // publish: one increment per (eighth, sample-block)
    __threadfence();
    __syncthreads();
    if (threadIdx.x == 0) atomicAdd(&g_ctr[blk], 1u);
}

// ------------------------------- merge path ---------------------------------
// 2 warps (side 0 = eighths 0..3, side 1 = 4..7), 32 sample-pairs per CTA.
__device__ __noinline__ void merge_path(int m, float* sw,
                                        const float* __restrict__ w2,
                                        const float* __restrict__ w1,
                                        const float* __restrict__ w0,
                                        float* __restrict__ out) {
    // stage weights while (possibly) waiting
    scopy4(sw + MW2, w2, 2048 / 4);
    scopy4(sw + MW1, w1, 1024 / 4);
    scopy4(sw + MW0, w0, 128 / 4);

    // counters guarding our samples: low [m*32, m*32+32), high +HALF
    const int lo = m * 32, hi = HALF + m * 32;
    int pidx;
    switch (threadIdx.x & 3) {
        case 0: pidx = lo / SPB;        break;
        case 1: pidx = (lo + 31) / SPB; break;
        case 2: pidx = hi / SPB;        break;
        default: pidx = (hi + 31) / SPB;
    }
    if (threadIdx.x < 4) {
        while (ld_acq(&g_ctr[pidx]) < 8u) __nanosleep(128);
    }
    __syncthreads();

    const int side = threadIdx.x >> 5;
    const int lane = threadIdx.x & 31;
    const int bA = lo + lane;
    const int bB = bA + HALF;
    const int eb = side * 4;

    float vA0[8], vA1[8], vB0[8], vB1[8];
    float qA0[8], qB0[8], hA[8], hB[8];

    load_pair(eb + 0, bA, vA0);
    load_pair(eb + 1, bA, vA1);
    load_pair(eb + 0, bB, vB0);
    load_pair(eb + 1, bB, vB1);
    contract888_2(vA0, vA1, vB0, vB1, sw + MW2 + (2 * side) * 512, qA0, qB0);

    load_pair(eb + 2, bA, vA0);
    load_pair(eb + 3, bA, vA1);
    load_pair(eb + 2, bB, vB0);
    load_pair(eb + 3, bB, vB1);
    contract888_2(vA0, vA1, vB0, vB1, sw + MW2 + (2 * side + 1) * 512, vA0, vB0);

    contract888_2(qA0, vA0, qB0, vB0, sw + MW1 + side * 512, hA, hB);

    // exchange
    if (side) {
#pragma unroll
        for (int k = 0; k < 8; ++k) sw[MXA + lane * 9 + k] = hA[k];
    } else {
#pragma unroll
        for (int k = 0; k < 8; ++k) sw[MXB + lane * 9 + k] = hB[k];
    }
    __syncthreads();

    float hL[8], hR[8];
    int bo;
    if (side == 0) {
#pragma unroll
        for (int k = 0; k < 8; ++k) { hL[k] = hA[k]; hR[k] = sw[MXA + lane * 9 + k]; }
        bo = bA;
    } else {
#pragma unroll
        for (int k = 0; k < 8; ++k) { hL[k] = sw[MXB + lane * 9 + k]; hR[k] = hB[k]; }
        bo = bB;
    }

    ull acc = 0ull;
#pragma unroll
    for (int i = 0; i < 8; ++i) {
        ull ai = bcast2(hL[i]);
#pragma unroll
        for (int j = 0; j < 8; ++j) {
            ull W = *reinterpret_cast<const ull*>(sw + MW0 + (i * 8 + j) * 2);
            acc = ffma2(ffma2(ai, bcast2(hR[j]), 0ull), W, acc);
        }
    }
    float r0, r1;
    unpack2(acc, r0, r1);
    reinterpret_cast<float2*>(out)[bo] = make_float2(r0, r1);
}

// --------------------------------- kernel -----------------------------------
__global__ void __launch_bounds__(T1, 5)
tn_fused_kernel(const float* __restrict__ x,
                const float* __restrict__ w7, const float* __restrict__ w6,
                const float* __restrict__ w5, const float* __restrict__ w4,
                const float* __restrict__ w3, const float* __restrict__ w2,
                const float* __restrict__ w1, const float* __restrict__ w0,
                float* __restrict__ out) {
    extern __shared__ float sw[];
    if (blockIdx.x < NPROD) {
        producer_path(blockIdx.x, sw, x, w7, w6, w5, w4, w3);
    } else {
        merge_path(blockIdx.x - NPROD, sw, w2, w1, w0, out);
    }
}

extern "C" void kernel_launch(void* const* d_in, const int* in_sizes, int n_in,
                              void* d_out, int out_size) {
    const float* x  = (const float*)d_in[0];
    const float* w7 = (const float*)d_in[1];
    const float* w6 = (const float*)d_in[2];
    const float* w5 = (const float*)d_in[3];
    const float* w4 = (const float*)d_in[4];
    const float* w3 = (const float*)d_in[5];
    const float* w2 = (const float*)d_in[6];
    const float* w1 = (const float*)d_in[7];
    const float* w0 = (const float*)d_in[8];
    float* out = (float*)d_out;

    // zero the producer-completion counters (graph-capturable memset node)
    void* ctr_ptr = nullptr;
    cudaGetSymbolAddress(&ctr_ptr, g_ctr);
    cudaMemsetAsync(ctr_ptr, 0, BLK_E * sizeof(unsigned int), 0);

    const size_t smem = SMEM_FLOATS * sizeof(float);
    cudaFuncSetAttribute(tn_fused_kernel, cudaFuncAttributeMaxDynamicSharedMemorySize, (int)smem);
    tn_fused_kernel<<<NBLOCKS, T1, smem>>>(x, w7, w6, w5, w4, w3, w2, w1, w0, out);
}